// round 3
// baseline (speedup 1.0000x reference)
#include <cuda_runtime.h>
#include <math.h>

typedef unsigned long long ull;

// Problem constants
constexpr int Bc = 2048;
constexpr int Tc = 13;
constexpr int Hc = 256;
constexpr int Mc = Bc * Tc;      // 26624 rows for the input GEMMs
// N of input GEMM = 1536 (both directions stacked: 2 * 768)

// Scratch (device globals: allocation-free rule)
__device__ float g_gx[(size_t)2 * Mc * 768];    // [dir][b*T+t][768]
__device__ float g_buf0[(size_t)Mc * 512];      // layer output ping
__device__ float g_buf1[(size_t)Mc * 512];      // layer output pong
__device__ float g_hsum[(size_t)2 * Bc * Hc];   // [dir][b][256] summed over layers

// ---------- packed f32x2 helpers (FFMA2: 2x fp32 FMA throughput on sm_103a) ----------
__device__ __forceinline__ ull pk2(float x, float y) {
    ull r; asm("mov.b64 %0, {%1,%2};" : "=l"(r) : "f"(x), "f"(y)); return r;
}
__device__ __forceinline__ float2 up2(ull v) {
    float2 f; asm("mov.b64 {%0,%1}, %2;" : "=f"(f.x), "=f"(f.y) : "l"(v)); return f;
}
__device__ __forceinline__ ull ffma2_(ull a, ull b, ull c) {
    ull d; asm("fma.rn.f32x2 %0, %1, %2, %3;" : "=l"(d) : "l"(a), "l"(b), "l"(c)); return d;
}
__device__ __forceinline__ float sigmf(float x) { return 1.f / (1.f + expf(-x)); }

// ---------- zero hsum ----------
__global__ void zero_hsum_kernel() {
    int i = blockIdx.x * blockDim.x + threadIdx.x;
    if (i < 2 * Bc * Hc) g_hsum[i] = 0.f;
}

// ---------- input GEMM: gx[d][m][g] = sum_k A[m][k] * W[d*768+g][k] + bias ----------
// A: Mc x K row-major. W: 1536 x K row-major. 128x128 tile, 256 threads, 8x8 microtile.
__global__ void __launch_bounds__(256, 2) gemm_gx_kernel(
    const float* __restrict__ Ax, int srcsel,
    const float* __restrict__ W, const float* __restrict__ bias, int K)
{
    const float* A = (srcsel == 2) ? Ax : (srcsel == 0 ? g_buf0 : g_buf1);

    __shared__ float As[16][132];
    __shared__ float Ws[16][132];

    const int tid = threadIdx.x;
    const int m0 = blockIdx.y * 128;
    const int n0 = blockIdx.x * 128;
    const int tm = (tid >> 4) << 3;   // 0..120
    const int tn = (tid & 15) << 3;   // 0..120

    ull acc[8][4];
#pragma unroll
    for (int i = 0; i < 8; i++)
#pragma unroll
        for (int j = 0; j < 4; j++) acc[i][j] = 0ull;

    const int nk = (K + 15) >> 4;
#pragma unroll 1
    for (int kc = 0; kc < nk; kc++) {
        const int k0 = kc << 4;
        __syncthreads();
        // cooperative load: A tile 128x16 and W tile 128x16, transposed into smem
#pragma unroll
        for (int i = 0; i < 2; i++) {
            int lin = tid + (i << 8);
            int r = lin >> 2;
            int c = lin & 3;
            int k = k0 + (c << 2);
            float4 va = make_float4(0.f, 0.f, 0.f, 0.f);
            float4 vw = make_float4(0.f, 0.f, 0.f, 0.f);
            if (k < K) {
                va = *(const float4*)&A[(size_t)(m0 + r) * K + k];
                vw = *(const float4*)&W[(size_t)(n0 + r) * K + k];
            }
            int kk = c << 2;
            As[kk + 0][r] = va.x; As[kk + 1][r] = va.y; As[kk + 2][r] = va.z; As[kk + 3][r] = va.w;
            Ws[kk + 0][r] = vw.x; Ws[kk + 1][r] = vw.y; Ws[kk + 2][r] = vw.z; Ws[kk + 3][r] = vw.w;
        }
        __syncthreads();
#pragma unroll
        for (int ki = 0; ki < 16; ki++) {
            float4 alo = *(const float4*)&As[ki][tm];
            float4 ahi = *(const float4*)&As[ki][tm + 4];
            ull a2[8];
            a2[0] = pk2(alo.x, alo.x); a2[1] = pk2(alo.y, alo.y);
            a2[2] = pk2(alo.z, alo.z); a2[3] = pk2(alo.w, alo.w);
            a2[4] = pk2(ahi.x, ahi.x); a2[5] = pk2(ahi.y, ahi.y);
            a2[6] = pk2(ahi.z, ahi.z); a2[7] = pk2(ahi.w, ahi.w);
            const ull* wrow = (const ull*)&Ws[ki][tn];
            ull w2[4] = { wrow[0], wrow[1], wrow[2], wrow[3] };
#pragma unroll
            for (int rr = 0; rr < 8; rr++)
#pragma unroll
                for (int cp = 0; cp < 4; cp++)
                    acc[rr][cp] = ffma2_(a2[rr], w2[cp], acc[rr][cp]);
        }
    }

    // epilogue: add bias, scatter to gx[dir][m][g]
    const int nbase = n0 + tn;          // 0..1528, group of 8 stays within one dir (768%8==0)
    const int d = nbase / 768;
    const int g = nbase % 768;
    float bia[8];
#pragma unroll
    for (int j = 0; j < 8; j++) bia[j] = bias[nbase + j];
#pragma unroll
    for (int rr = 0; rr < 8; rr++) {
        int m = m0 + tm + rr;
        float* op = g_gx + ((size_t)d * Mc + m) * 768 + g;
        float2 p0 = up2(acc[rr][0]), p1 = up2(acc[rr][1]);
        float2 p2 = up2(acc[rr][2]), p3 = up2(acc[rr][3]);
        float4 o0 = make_float4(p0.x + bia[0], p0.y + bia[1], p1.x + bia[2], p1.y + bia[3]);
        float4 o1 = make_float4(p2.x + bia[4], p2.y + bia[5], p3.x + bia[6], p3.y + bia[7]);
        *(float4*)&op[0] = o0;
        *(float4*)&op[4] = o1;
    }
}

// ---------- GRU recurrence: one block = 32 batch rows, loops all T steps ----------
constexpr int ROWS = 32;
constexpr int HPITCH = 260;
constexpr int WPITCH = 772;
constexpr int RECUR_SMEM = (ROWS * HPITCH + 16 * WPITCH) * 4;  // 82688 B

__global__ void __launch_bounds__(256, 1) gru_recur_kernel(
    const float* __restrict__ Whh_all, const float* __restrict__ bhh_all,
    int layer, int dstsel)
{
    extern __shared__ float smem[];
    float* h_s = smem;                    // [32][HPITCH]
    float* w_s = smem + ROWS * HPITCH;    // [16][WPITCH]
    float* outbuf = dstsel ? g_buf1 : g_buf0;

    const int tid = threadIdx.x;
    const int dir = blockIdx.y;
    const int b0 = blockIdx.x * ROWS;
    const float* W   = Whh_all + (size_t)(layer * 2 + dir) * 768 * 256;
    const float* bhh = bhh_all + (size_t)(layer * 2 + dir) * 768;
    const float* gxd = g_gx + (size_t)dir * Mc * 768;

    const int r0 = (tid >> 6) << 3;   // 8-row group: 0,8,16,24
    const int j0 = (tid & 63) << 2;   // 4-col group: 0..252

    // preload recurrent biases for this thread's columns (step-invariant)
    float2 bh[3][2];
#pragma unroll
    for (int gi = 0; gi < 3; gi++)
#pragma unroll
        for (int cp = 0; cp < 2; cp++)
            bh[gi][cp] = *(const float2*)&bhh[gi * 256 + j0 + (cp << 1)];

    // h0 = 0
    for (int i = tid; i < ROWS * HPITCH; i += 256) h_s[i] = 0.f;
    __syncthreads();

#pragma unroll 1
    for (int step = 0; step < Tc; step++) {
        const int tg = dir ? (Tc - 1 - step) : step;

        ull acc[3][8][2];
#pragma unroll
        for (int gi = 0; gi < 3; gi++)
#pragma unroll
            for (int rr = 0; rr < 8; rr++) { acc[gi][rr][0] = 0ull; acc[gi][rr][1] = 0ull; }

#pragma unroll 1
        for (int kc = 0; kc < 16; kc++) {
            const int k0 = kc << 4;
            __syncthreads();   // protect w_s reuse (and h_s writes from prev step on kc==0)
            // stage W[0:768][k0:k0+16] transposed -> w_s[k][g]
#pragma unroll
            for (int i = 0; i < 12; i++) {
                int lin = tid + (i << 8);        // 0..3071
                int g = lin >> 2;
                int f = lin & 3;
                float4 v = *(const float4*)&W[(size_t)g * 256 + k0 + (f << 2)];
                int kk = f << 2;
                w_s[(kk + 0) * WPITCH + g] = v.x;
                w_s[(kk + 1) * WPITCH + g] = v.y;
                w_s[(kk + 2) * WPITCH + g] = v.z;
                w_s[(kk + 3) * WPITCH + g] = v.w;
            }
            __syncthreads();
#pragma unroll
            for (int ki = 0; ki < 16; ki++) {
                const int k = k0 + ki;
                ull a2[8];
#pragma unroll
                for (int rr = 0; rr < 8; rr++) {
                    float hv = h_s[(r0 + rr) * HPITCH + k];
                    a2[rr] = pk2(hv, hv);
                }
                const float* wr = w_s + ki * WPITCH;
                ull w2[6];
#pragma unroll
                for (int gi = 0; gi < 3; gi++) {
                    w2[gi * 2 + 0] = *(const ull*)(wr + gi * 256 + j0);
                    w2[gi * 2 + 1] = *(const ull*)(wr + gi * 256 + j0 + 2);
                }
#pragma unroll
                for (int gi = 0; gi < 3; gi++)
#pragma unroll
                    for (int rr = 0; rr < 8; rr++)
#pragma unroll
                        for (int cp = 0; cp < 2; cp++)
                            acc[gi][rr][cp] = ffma2_(a2[rr], w2[gi * 2 + cp], acc[gi][rr][cp]);
            }
        }

        // gate math (registers only; reads gx + own h cells)
        float2 hnew[8][2];
#pragma unroll
        for (int rr = 0; rr < 8; rr++) {
            const int row = r0 + rr;
            const int b = b0 + row;
            const float* gxrow = gxd + ((size_t)b * Tc + tg) * 768;
#pragma unroll
            for (int cp = 0; cp < 2; cp++) {
                const int j = j0 + (cp << 1);
                float2 xr = *(const float2*)&gxrow[j];
                float2 xz = *(const float2*)&gxrow[256 + j];
                float2 xn = *(const float2*)&gxrow[512 + j];
                float2 gr = up2(acc[0][rr][cp]);
                float2 gz = up2(acc[1][rr][cp]);
                float2 gn = up2(acc[2][rr][cp]);
                float2 hp = *(const float2*)&h_s[row * HPITCH + j];
                float rx = sigmf(xr.x + gr.x + bh[0][cp].x);
                float ry = sigmf(xr.y + gr.y + bh[0][cp].y);
                float zx = sigmf(xz.x + gz.x + bh[1][cp].x);
                float zy = sigmf(xz.y + gz.y + bh[1][cp].y);
                float nx = tanhf(xn.x + rx * (gn.x + bh[2][cp].x));
                float ny = tanhf(xn.y + ry * (gn.y + bh[2][cp].y));
                hnew[rr][cp].x = (1.f - zx) * nx + zx * hp.x;
                hnew[rr][cp].y = (1.f - zy) * ny + zy * hp.y;
            }
        }
        __syncthreads();   // everyone done reading old h
#pragma unroll
        for (int rr = 0; rr < 8; rr++) {
            const int row = r0 + rr;
            const int b = b0 + row;
            float4 hv = make_float4(hnew[rr][0].x, hnew[rr][0].y, hnew[rr][1].x, hnew[rr][1].y);
            *(float4*)&h_s[row * HPITCH + j0] = hv;
            float* op = outbuf + ((size_t)b * Tc + tg) * 512 + dir * 256 + j0;
            *(float4*)op = hv;
            if (step == Tc - 1) {
                float* hp = g_hsum + ((size_t)dir * Bc + b) * 256 + j0;
                float4 cur = *(const float4*)hp;
                cur.x += hv.x; cur.y += hv.y; cur.z += hv.z; cur.w += hv.w;
                *(float4*)hp = cur;
            }
        }
        // next iteration starts with __syncthreads() inside the kc loop
    }
}

// ---------- head: mean over 16 finals -> silu MLP -> scalar ----------
__global__ void head_kernel(const float* __restrict__ W1, const float* __restrict__ b1,
                            const float* __restrict__ W2, const float* __restrict__ b2,
                            const float* __restrict__ Wc, const float* __restrict__ bc,
                            float* __restrict__ out)
{
    const int b = blockIdx.x;
    const int tid = threadIdx.x;   // 64 threads
    __shared__ float hs[256];
    __shared__ float s1[64];
    for (int i = tid; i < 256; i += 64)
        hs[i] = (g_hsum[(size_t)b * 256 + i] + g_hsum[(size_t)(Bc + b) * 256 + i]) * (1.f / 16.f);
    __syncthreads();
    float a1 = b1[tid];
    const float* w1r = W1 + (size_t)tid * 256;
#pragma unroll 4
    for (int k = 0; k < 256; k++) a1 += hs[k] * w1r[k];
    s1[tid] = a1 * sigmf(a1);
    __syncthreads();
    if (tid < 32) {
        float a2 = b2[tid];
        const float* w2r = W2 + (size_t)tid * 64;
#pragma unroll
        for (int k = 0; k < 64; k++) a2 += s1[k] * w2r[k];
        float y = a2 * sigmf(a2);
        float v = y * Wc[tid];
#pragma unroll
        for (int o = 16; o > 0; o >>= 1) v += __shfl_down_sync(0xffffffffu, v, o);
        if (tid == 0) out[b] = v + bc[0];
    }
}

// ---------- launch ----------
extern "C" void kernel_launch(void* const* d_in, const int* in_sizes, int n_in,
                              void* d_out, int out_size) {
    (void)in_sizes; (void)n_in; (void)out_size;
    const float* x         = (const float*)d_in[0];
    const float* W_ih0     = (const float*)d_in[1];
    const float* W_ih_rest = (const float*)d_in[2];
    const float* W_hh      = (const float*)d_in[3];
    const float* b_ih      = (const float*)d_in[4];
    const float* b_hh      = (const float*)d_in[5];
    const float* W1        = (const float*)d_in[6];
    const float* b1        = (const float*)d_in[7];
    const float* W2        = (const float*)d_in[8];
    const float* b2        = (const float*)d_in[9];
    const float* Wc        = (const float*)d_in[10];
    const float* bc        = (const float*)d_in[11];
    float* out = (float*)d_out;

    cudaFuncSetAttribute(gru_recur_kernel,
                         cudaFuncAttributeMaxDynamicSharedMemorySize, RECUR_SMEM);

    zero_hsum_kernel<<<(2 * Bc * Hc + 255) / 256, 256>>>();

    dim3 ggrid(12, 208);       // N/128, M/128
    dim3 rgrid(Bc / ROWS, 2);  // 64 x 2 dirs

    for (int l = 0; l < 8; l++) {
        const float* Wi = (l == 0) ? W_ih0 : (W_ih_rest + (size_t)(l - 1) * 2 * 768 * 512);
        const int K = (l == 0) ? 188 : 512;
        const int srcsel = (l == 0) ? 2 : ((l - 1) & 1);
        gemm_gx_kernel<<<ggrid, 256>>>(x, srcsel, Wi, b_ih + (size_t)l * 1536, K);
        gru_recur_kernel<<<rgrid, 256, RECUR_SMEM>>>(W_hh, b_hh, l, l & 1);
    }

    head_kernel<<<Bc, 64>>>(W1, b1, W2, b2, Wc, bc, out);
}